// round 15
// baseline (speedup 1.0000x reference)
#include <cuda_runtime.h>
#include <cuda_bf16.h>
#include <cstdint>

#define BS 16
#define NN 512
#define DD 256
#define RR 2
#define M_TOTAL (BS * NN)           // 8192
#define K_TOTAL (3 * DD)            // 768
#define BKT 16                      // GEMM K-tile
#define NT (K_TOTAL / BKT)          // 48 tiles
#define STG 3                       // GEMM cp.async stages
#define ACAT_L ((size_t)M_TOTAL * K_TOTAL)
#define W_L    ((size_t)K_TOTAL * DD)

// Scratch (no allocations allowed).
__device__ __align__(16) unsigned short g_list[(size_t)BS * NN * NN];  // per (b,j): r0 front, r1 back
__device__ int   g_cnt[RR][BS * NN];
__device__ float g_inv[RR][BS * NN];
__device__ __align__(16) uint32_t g_acat[2 * ACAT_L];   // tf32 [layer][m][768] = [x|agg0|agg1]
__device__ __align__(16) uint32_t g_w[2 * W_L];         // tf32 [layer][768][256]

__device__ __forceinline__ uint32_t f2tf32(float f) {
    uint32_t u;
    asm("cvt.rna.tf32.f32 %0, %1;" : "=r"(u) : "f"(f));
    return u;
}

__device__ __forceinline__ void cp16(uint32_t dst, const void* src) {
    asm volatile("cp.async.cg.shared.global [%0], [%1], 16;"
                 :: "r"(dst), "l"(src));
}

// ---------------------------------------------------------------------------
// Kernel 1: fused prologue. Blocks [0,256): mask transpose + compact
// neighbor-list build. Blocks [256,768): tf32 conversion of x + weights.
// Adjacency is int32 on device (JAX downcasts int64).
// bit0 = punct (punct==1 && aug!=1), bit1 = aug (aug==1).
// ---------------------------------------------------------------------------
#define SMROW 516
#define LIST_BLOCKS 256
#define CVT_BLOCKS 512
#define XF4 (M_TOTAL * DD / 4)
#define WF4L (K_TOTAL * DD / 4)
#define ROOTF4 (DD * DD / 4)

__global__ void __launch_bounds__(256)
prologue_kernel(const int* __restrict__ aug,
                const int* __restrict__ punct,
                const float* __restrict__ x,
                const float* __restrict__ wroot1,
                const float* __restrict__ wrel1,
                const float* __restrict__ wroot2,
                const float* __restrict__ wrel2) {
    __shared__ unsigned char sm[32 * SMROW];
    const int t = threadIdx.x;

    if (blockIdx.x >= LIST_BLOCKS) {
        // ----- cvt job -----
        const int total = XF4 + 2 * WF4L;
        const int bid = blockIdx.x - LIST_BLOCKS;
        for (int idx = bid * 256 + t; idx < total; idx += CVT_BLOCKS * 256) {
            float4 v;
            uint32_t* dst;
            if (idx < XF4) {
                const int m = idx >> 6;
                const int dq = idx & 63;
                v = ((const float4*)x)[idx];
                dst = g_acat + (size_t)m * K_TOTAL + dq * 4;
            } else {
                const int j = idx - XF4;
                const int L = j / WF4L;
                const int j2 = j - L * WF4L;
                const float4* src = (j2 < ROOTF4)
                    ? ((const float4*)(L ? wroot2 : wroot1)) + j2
                    : ((const float4*)(L ? wrel2 : wrel1)) + (j2 - ROOTF4);
                v = *src;
                dst = g_w + (size_t)L * W_L + (size_t)j2 * 4;
            }
            uint4 u;
            u.x = f2tf32(v.x); u.y = f2tf32(v.y);
            u.z = f2tf32(v.z); u.w = f2tf32(v.w);
            *(uint4*)dst = u;
        }
        return;
    }

    // ----- list job -----
    const int jt = blockIdx.x & 15;
    const int b  = blockIdx.x >> 4;
    const int w  = t >> 5;
    const int lane = t & 31;
    const int j0 = jt * 32;
    const size_t base = (size_t)b * NN * NN;

    const int i0w = w * 64;
    #pragma unroll 4
    for (int s = 0; s < 64; s++) {
        const int i = i0w + s;
        const size_t idx = base + (size_t)i * NN + j0 + lane;
        const int a = aug[idx];
        const int p = punct[idx];
        sm[lane * SMROW + i] = (a == 1) ? (unsigned char)2
                                        : ((p == 1) ? (unsigned char)1
                                                    : (unsigned char)0);
    }
    __syncthreads();

    const unsigned lt = (1u << lane) - 1u;
    #pragma unroll
    for (int q = 0; q < 4; q++) {
        const int jl = w * 4 + q;
        const unsigned char* __restrict__ row = sm + jl * SMROW;
        const size_t o = (size_t)b * NN + j0 + jl;
        unsigned short* __restrict__ lst = g_list + o * NN;

        int c0 = 0, c1 = 0;
        #pragma unroll 4
        for (int s = 0; s < NN; s += 32) {
            const unsigned char m = row[s + lane];
            const unsigned b0 = __ballot_sync(0xffffffffu, m & 1);
            const unsigned b1 = __ballot_sync(0xffffffffu, m & 2);
            if (m & 1) lst[c0 + __popc(b0 & lt)] = (unsigned short)(s + lane);
            if (m & 2) lst[NN - 1 - (c1 + __popc(b1 & lt))] = (unsigned short)(s + lane);
            c0 += __popc(b0);
            c1 += __popc(b1);
        }
        if (lane == 0) {
            g_cnt[0][o] = c0;
            g_cnt[1][o] = c1;
            g_inv[0][o] = 1.0f / (float)max(c0, 1);
            g_inv[1][o] = 1.0f / (float)max(c1, 1);
        }
    }
}

// ---------------------------------------------------------------------------
// Kernel 2: sparse mean-aggregation via compact lists.
// Block = (j, b), 64 threads; thread owns channels [4t,4t+3] (float4).
// layer 0 reads x (row stride 256); layer 1 reads acat[1] seg0 (tf32 bits,
// row stride 768). Writes tf32 into g_acat[layer] segments 1 and 2.
// ---------------------------------------------------------------------------
__global__ void __launch_bounds__(64)
aggregate_kernel(const float* __restrict__ x, int layer) {
    const int j = blockIdx.x;
    const int b = blockIdx.y;
    const int t = threadIdx.x;
    const size_t o = (size_t)b * NN + j;

    __shared__ alignas(8) unsigned short slist[NN];
    __shared__ int sn0, sn1;
    __shared__ float si0, si1;
    if (t == 0) {
        sn0 = g_cnt[0][o]; sn1 = g_cnt[1][o];
        si0 = g_inv[0][o]; si1 = g_inv[1][o];
    }
    const unsigned short* __restrict__ lst = g_list + o * NN;
    #pragma unroll
    for (int k = 0; k < NN / 2 / 64; k++)
        ((unsigned int*)slist)[t + k * 64] = ((const unsigned int*)lst)[t + k * 64];
    __syncthreads();

    const int n0 = sn0, n1 = sn1;
    const float inv0 = si0, inv1 = si1;
    const int rs = layer ? (K_TOTAL / 4) : (DD / 4);
    const float4* __restrict__ xb = layer
        ? (const float4*)(g_acat + ACAT_L + (size_t)b * NN * K_TOTAL)
        : (const float4*)(x + (size_t)b * NN * DD);

    float4 p0 = make_float4(0.f, 0.f, 0.f, 0.f);
    float4 p1 = make_float4(0.f, 0.f, 0.f, 0.f);
    int k = 0;
    for (; k + 4 <= n0; k += 4) {
        const uint32_t w0 = *(const uint32_t*)&slist[k];
        const uint32_t w1 = *(const uint32_t*)&slist[k + 2];
        const float4 v0 = xb[(w0 & 0xffffu) * rs + t];
        const float4 v1 = xb[(w0 >> 16)     * rs + t];
        const float4 v2 = xb[(w1 & 0xffffu) * rs + t];
        const float4 v3 = xb[(w1 >> 16)     * rs + t];
        p0.x += v0.x + v2.x; p0.y += v0.y + v2.y;
        p0.z += v0.z + v2.z; p0.w += v0.w + v2.w;
        p1.x += v1.x + v3.x; p1.y += v1.y + v3.y;
        p1.z += v1.z + v3.z; p1.w += v1.w + v3.w;
    }
    for (; k < n0; k++) {
        const float4 v = xb[slist[k] * rs + t];
        p0.x += v.x; p0.y += v.y; p0.z += v.z; p0.w += v.w;
    }
    float4 a0 = make_float4(p0.x + p1.x, p0.y + p1.y, p0.z + p1.z, p0.w + p1.w);

    float4 q0 = make_float4(0.f, 0.f, 0.f, 0.f);
    float4 q1 = make_float4(0.f, 0.f, 0.f, 0.f);
    k = 0;
    for (; k + 4 <= n1; k += 4) {
        const int i0 = slist[NN - 1 - k];
        const int i1 = slist[NN - 2 - k];
        const int i2 = slist[NN - 3 - k];
        const int i3 = slist[NN - 4 - k];
        const float4 v0 = xb[i0 * rs + t];
        const float4 v1 = xb[i1 * rs + t];
        const float4 v2 = xb[i2 * rs + t];
        const float4 v3 = xb[i3 * rs + t];
        q0.x += v0.x + v2.x; q0.y += v0.y + v2.y;
        q0.z += v0.z + v2.z; q0.w += v0.w + v2.w;
        q1.x += v1.x + v3.x; q1.y += v1.y + v3.y;
        q1.z += v1.z + v3.z; q1.w += v1.w + v3.w;
    }
    for (; k < n1; k++) {
        const float4 v = xb[slist[NN - 1 - k] * rs + t];
        q0.x += v.x; q0.y += v.y; q0.z += v.z; q0.w += v.w;
    }
    float4 a1 = make_float4(q0.x + q1.x, q0.y + q1.y, q0.z + q1.z, q0.w + q1.w);

    uint32_t* __restrict__ base =
        g_acat + (size_t)layer * ACAT_L + o * K_TOTAL;
    uint4 u0, u1;
    u0.x = f2tf32(a0.x * inv0); u0.y = f2tf32(a0.y * inv0);
    u0.z = f2tf32(a0.z * inv0); u0.w = f2tf32(a0.w * inv0);
    u1.x = f2tf32(a1.x * inv1); u1.y = f2tf32(a1.y * inv1);
    u1.z = f2tf32(a1.z * inv1); u1.w = f2tf32(a1.w * inv1);
    ((uint4*)(base + DD))[t]     = u0;
    ((uint4*)(base + 2 * DD))[t] = u1;
}

// ---------------------------------------------------------------------------
// Kernel 3: TF32 tensor-core GEMM + bias + ELU, cp.async 3-stage pipeline.
//   out[m,e] = elu( Acat[m,:] @ W[:,e] + bias[e] )
// M=8192, K=768, N=256. Block tile 64x128, 8 warps (2M x 4N), warp 32x32 —
// 2x warps vs the 4-warp version to raise per-SMSP warp count (latency hide).
// BSTR=136: fragment bank = (8*tig + gid) % 32 -> conflict-free.
// layer 0: writes ONLY tf32 seg0 of acat[1]. layer 1: writes dout (fp32).
// ---------------------------------------------------------------------------
__device__ __forceinline__ void mma_tf32(float c[4], const uint32_t a[4],
                                         uint32_t b0, uint32_t b1) {
    asm volatile(
        "mma.sync.aligned.m16n8k8.row.col.f32.tf32.tf32.f32 "
        "{%0,%1,%2,%3}, {%4,%5,%6,%7}, {%8,%9}, {%0,%1,%2,%3};"
        : "+f"(c[0]), "+f"(c[1]), "+f"(c[2]), "+f"(c[3])
        : "r"(a[0]), "r"(a[1]), "r"(a[2]), "r"(a[3]), "r"(b0), "r"(b1));
}

#define ASTR 20
#define BSTR 136

__global__ void __launch_bounds__(256)
rgcn_gemm_kernel(int layer, const float* __restrict__ bias,
                 float* __restrict__ dout) {
    __shared__ uint32_t As[STG][64][ASTR];    // [stage][m][k]
    __shared__ uint32_t Bs[STG][BKT][BSTR];   // [stage][k][n]

    const uint32_t* __restrict__ Ag = g_acat + (size_t)layer * ACAT_L;
    const uint32_t* __restrict__ Bg = g_w + (size_t)layer * W_L;

    const int t    = threadIdx.x;
    const int lane = t & 31;
    const int wid  = t >> 5;
    const int wm   = wid & 1;          // warp M index (0..1)
    const int wn   = wid >> 1;         // warp N index (0..3)
    const int gid  = lane >> 2;
    const int tig  = lane & 3;
    const int m0   = blockIdx.y * 64;
    const int e0   = blockIdx.x * 128;

    const uint32_t asb = (uint32_t)__cvta_generic_to_shared(As);
    const uint32_t bsb = (uint32_t)__cvta_generic_to_shared(Bs);

    // copy mappings (256 threads)
    const int ar0 = t >> 2;            // A row 0..63, one cp16 each
    const int ako = (t & 3) << 2;      // k offset 0/4/8/12
    const int br0 = t >> 4;            // B k-row 0..15
    const int bno = (t & 15) << 3;     // n offset 0..120, two cp16 each

    auto issue_tile = [&](int tile) {
        if (tile < NT) {
            const int stage = tile % STG;
            const int kg = tile * BKT;
            cp16(asb + (uint32_t)(((stage * 64 + ar0) * ASTR + ako) * 4),
                 Ag + (size_t)(m0 + ar0) * K_TOTAL + kg + ako);
            #pragma unroll
            for (int i = 0; i < 2; i++) {
                cp16(bsb + (uint32_t)(((stage * BKT + br0) * BSTR + bno + 4 * i) * 4),
                     Bg + (size_t)(kg + br0) * DD + e0 + bno + 4 * i);
            }
        }
        asm volatile("cp.async.commit_group;");
    };

    issue_tile(0);
    issue_tile(1);

    float acc[2][4][4] = {};

    for (int kt = 0; kt < NT; kt++) {
        asm volatile("cp.async.wait_group %0;" :: "n"(STG - 2));
        __syncthreads();

        issue_tile(kt + STG - 1);

        const int st = kt % STG;
        #pragma unroll
        for (int ks = 0; ks < 2; ks++) {
            const int kb = ks * 8;
            uint32_t af[2][4];
            #pragma unroll
            for (int mt = 0; mt < 2; mt++) {
                const int m = wm * 32 + mt * 16 + gid;
                af[mt][0] = As[st][m][kb + tig];
                af[mt][1] = As[st][m + 8][kb + tig];
                af[mt][2] = As[st][m][kb + tig + 4];
                af[mt][3] = As[st][m + 8][kb + tig + 4];
            }
            #pragma unroll
            for (int nt = 0; nt < 4; nt++) {
                const int n = wn * 32 + nt * 8 + gid;
                const uint32_t b0 = Bs[st][kb + tig][n];
                const uint32_t b1 = Bs[st][kb + tig + 4][n];
                mma_tf32(acc[0][nt], af[0], b0, b1);
                mma_tf32(acc[1][nt], af[1], b0, b1);
            }
        }
    }

    // epilogue: bias + ELU
    uint32_t* __restrict__ outt = g_acat + ACAT_L;   // layer-1 seg0 (tf32)
    const float2* __restrict__ bias2 = (const float2*)bias;

    #pragma unroll
    for (int mt = 0; mt < 2; mt++) {
        const int mrow = m0 + wm * 32 + mt * 16 + gid;
        #pragma unroll
        for (int nt = 0; nt < 4; nt++) {
            const int col = e0 + wn * 32 + nt * 8 + 2 * tig;
            const float2 bb = bias2[col >> 1];
            float v0 = acc[mt][nt][0] + bb.x;
            float v1 = acc[mt][nt][1] + bb.y;
            float v2 = acc[mt][nt][2] + bb.x;
            float v3 = acc[mt][nt][3] + bb.y;
            v0 = (v0 > 0.f) ? v0 : expm1f(v0);
            v1 = (v1 > 0.f) ? v1 : expm1f(v1);
            v2 = (v2 > 0.f) ? v2 : expm1f(v2);
            v3 = (v3 > 0.f) ? v3 : expm1f(v3);
            if (layer == 0) {
                uint2 u0; u0.x = f2tf32(v0); u0.y = f2tf32(v1);
                uint2 u1; u1.x = f2tf32(v2); u1.y = f2tf32(v3);
                *(uint2*)&outt[(size_t)mrow * K_TOTAL + col]       = u0;
                *(uint2*)&outt[(size_t)(mrow + 8) * K_TOTAL + col] = u1;
            } else {
                *(float2*)&dout[(size_t)mrow * DD + col]       = make_float2(v0, v1);
                *(float2*)&dout[(size_t)(mrow + 8) * DD + col] = make_float2(v2, v3);
            }
        }
    }
}

// ---------------------------------------------------------------------------
// Launch: fused prologue, then per layer: agg -> TF32 GEMM+bias+ELU.
// ---------------------------------------------------------------------------
extern "C" void kernel_launch(void* const* d_in, const int* in_sizes, int n_in,
                              void* d_out, int out_size) {
    const float* x       = (const float*)d_in[0];
    const float* w_rel1  = (const float*)d_in[1];
    const float* w_root1 = (const float*)d_in[2];
    const float* b1      = (const float*)d_in[3];
    const float* w_rel2  = (const float*)d_in[4];
    const float* w_root2 = (const float*)d_in[5];
    const float* b2      = (const float*)d_in[6];
    const int* aug   = (const int*)d_in[7];
    const int* punct = (const int*)d_in[8];
    float* out = (float*)d_out;

    prologue_kernel<<<LIST_BLOCKS + CVT_BLOCKS, 256>>>(
        aug, punct, x, w_root1, w_rel1, w_root2, w_rel2);

    // Layer 1
    aggregate_kernel<<<dim3(NN, BS), 64>>>(x, 0);
    rgcn_gemm_kernel<<<dim3(DD / 128, M_TOTAL / 64), 256>>>(0, b1, nullptr);

    // Layer 2
    aggregate_kernel<<<dim3(NN, BS), 64>>>(nullptr, 1);
    rgcn_gemm_kernel<<<dim3(DD / 128, M_TOTAL / 64), 256>>>(1, b2, out);
}

// round 16
// speedup vs baseline: 1.2635x; 1.2635x over previous
#include <cuda_runtime.h>
#include <cuda_fp16.h>
#include <cstdint>

#define BS 16
#define NN 512
#define DD 256
#define RR 2
#define M_TOTAL (BS * NN)           // 8192
#define K_TOTAL (3 * DD)            // 768
#define BKT 32                      // GEMM K-tile (2 x k16 steps)
#define NT (K_TOTAL / BKT)          // 24 tiles
#define STG 3                       // cp.async stages
#define ACAT_L ((size_t)M_TOTAL * K_TOTAL)
#define W_L    ((size_t)K_TOTAL * DD)

// Scratch (no allocations allowed).
__device__ __align__(16) unsigned short g_list[(size_t)BS * NN * NN];  // per (b,j): r0 front, r1 back
__device__ int    g_cnt[RR][BS * NN];
__device__ float  g_inv[RR][BS * NN];
__device__ __align__(16) __half g_acat[2 * ACAT_L];   // fp16 [layer][m][768] = [x|agg0|agg1]
__device__ __align__(16) __half g_wT[2 * W_L];        // fp16 [layer][n=256][k=768] (K-major)

__device__ __forceinline__ void cp16(uint32_t dst, const void* src) {
    asm volatile("cp.async.cg.shared.global [%0], [%1], 16;"
                 :: "r"(dst), "l"(src));
}

// ---------------------------------------------------------------------------
// Kernel 1: fused prologue. Blocks [0,256): mask transpose + compact
// neighbor-list build. Blocks [256,768): fp16 conversion of x (acat[0] seg0)
// + weights (transposed to [n][k] K-major for the fp16 MMA B operand).
// Adjacency is int32 on device (JAX downcasts int64).
// bit0 = punct (punct==1 && aug!=1), bit1 = aug (aug==1).
// ---------------------------------------------------------------------------
#define SMROW 516
#define LIST_BLOCKS 256
#define CVT_BLOCKS 512
#define XF4 (M_TOTAL * DD / 4)
#define WF4L (K_TOTAL * DD / 4)

__global__ void __launch_bounds__(256)
prologue_kernel(const int* __restrict__ aug,
                const int* __restrict__ punct,
                const float* __restrict__ x,
                const float* __restrict__ wroot1,
                const float* __restrict__ wrel1,
                const float* __restrict__ wroot2,
                const float* __restrict__ wrel2) {
    __shared__ unsigned char sm[32 * SMROW];
    const int t = threadIdx.x;

    if (blockIdx.x >= LIST_BLOCKS) {
        // ----- cvt job -----
        const int total = XF4 + 2 * WF4L;
        const int bid = blockIdx.x - LIST_BLOCKS;
        for (int idx = bid * 256 + t; idx < total; idx += CVT_BLOCKS * 256) {
            if (idx < XF4) {
                const int m = idx >> 6;
                const int dq = idx & 63;
                const float4 v = ((const float4*)x)[idx];
                __half2 h0 = __floats2half2_rn(v.x, v.y);
                __half2 h1 = __floats2half2_rn(v.z, v.w);
                uint2 u;
                u.x = *(uint32_t*)&h0;
                u.y = *(uint32_t*)&h1;
                *(uint2*)&g_acat[(size_t)m * K_TOTAL + dq * 4] = u;
            } else {
                const int j = idx - XF4;
                const int L = j / WF4L;
                const int j2 = j - L * WF4L;
                const int kk = j2 >> 6;            // 0..767
                const int nn = (j2 & 63) << 2;     // n base
                const float* src = (kk < DD)
                    ? (L ? wroot2 : wroot1) + kk * DD + nn
                    : (L ? wrel2 : wrel1) + (size_t)(kk - DD) * DD + nn;
                const float4 v = *(const float4*)src;
                __half* dst = g_wT + (size_t)L * W_L;
                dst[(size_t)(nn + 0) * K_TOTAL + kk] = __float2half_rn(v.x);
                dst[(size_t)(nn + 1) * K_TOTAL + kk] = __float2half_rn(v.y);
                dst[(size_t)(nn + 2) * K_TOTAL + kk] = __float2half_rn(v.z);
                dst[(size_t)(nn + 3) * K_TOTAL + kk] = __float2half_rn(v.w);
            }
        }
        return;
    }

    // ----- list job -----
    const int jt = blockIdx.x & 15;
    const int b  = blockIdx.x >> 4;
    const int w  = t >> 5;
    const int lane = t & 31;
    const int j0 = jt * 32;
    const size_t base = (size_t)b * NN * NN;

    const int i0w = w * 64;
    #pragma unroll 4
    for (int s = 0; s < 64; s++) {
        const int i = i0w + s;
        const size_t idx = base + (size_t)i * NN + j0 + lane;
        const int a = aug[idx];
        const int p = punct[idx];
        sm[lane * SMROW + i] = (a == 1) ? (unsigned char)2
                                        : ((p == 1) ? (unsigned char)1
                                                    : (unsigned char)0);
    }
    __syncthreads();

    const unsigned lt = (1u << lane) - 1u;
    #pragma unroll
    for (int q = 0; q < 4; q++) {
        const int jl = w * 4 + q;
        const unsigned char* __restrict__ row = sm + jl * SMROW;
        const size_t o = (size_t)b * NN + j0 + jl;
        unsigned short* __restrict__ lst = g_list + o * NN;

        int c0 = 0, c1 = 0;
        #pragma unroll 4
        for (int s = 0; s < NN; s += 32) {
            const unsigned char m = row[s + lane];
            const unsigned b0 = __ballot_sync(0xffffffffu, m & 1);
            const unsigned b1 = __ballot_sync(0xffffffffu, m & 2);
            if (m & 1) lst[c0 + __popc(b0 & lt)] = (unsigned short)(s + lane);
            if (m & 2) lst[NN - 1 - (c1 + __popc(b1 & lt))] = (unsigned short)(s + lane);
            c0 += __popc(b0);
            c1 += __popc(b1);
        }
        if (lane == 0) {
            g_cnt[0][o] = c0;
            g_cnt[1][o] = c1;
            g_inv[0][o] = 1.0f / (float)max(c0, 1);
            g_inv[1][o] = 1.0f / (float)max(c1, 1);
        }
    }
}

// ---------------------------------------------------------------------------
// Kernel 2: sparse mean-aggregation via compact lists, fp16 I/O.
// Block = (j, b), 64 threads; thread owns channels [4t,4t+3].
// Reads acat[layer] seg0 (fp16, row stride 768); accumulates fp32; writes
// fp16 into acat[layer] segments 1 and 2.
// ---------------------------------------------------------------------------
__device__ __forceinline__ void acc4(float4& a, uint2 w) {
    const __half2 h0 = *(__half2*)&w.x;
    const __half2 h1 = *(__half2*)&w.y;
    const float2 f0 = __half22float2(h0);
    const float2 f1 = __half22float2(h1);
    a.x += f0.x; a.y += f0.y; a.z += f1.x; a.w += f1.y;
}

__global__ void __launch_bounds__(64)
aggregate_kernel(int layer) {
    const int j = blockIdx.x;
    const int b = blockIdx.y;
    const int t = threadIdx.x;
    const size_t o = (size_t)b * NN + j;

    __shared__ alignas(8) unsigned short slist[NN];
    __shared__ int sn0, sn1;
    __shared__ float si0, si1;
    if (t == 0) {
        sn0 = g_cnt[0][o]; sn1 = g_cnt[1][o];
        si0 = g_inv[0][o]; si1 = g_inv[1][o];
    }
    const unsigned short* __restrict__ lst = g_list + o * NN;
    #pragma unroll
    for (int k = 0; k < NN / 2 / 64; k++)
        ((unsigned int*)slist)[t + k * 64] = ((const unsigned int*)lst)[t + k * 64];
    __syncthreads();

    const int n0 = sn0, n1 = sn1;
    const float inv0 = si0, inv1 = si1;
    const __half* __restrict__ xb =
        g_acat + (size_t)layer * ACAT_L + (size_t)b * NN * K_TOTAL;
    const int ch = t * 4;   // channel base

    float4 p0 = make_float4(0.f, 0.f, 0.f, 0.f);
    float4 p1 = make_float4(0.f, 0.f, 0.f, 0.f);
    int k = 0;
    for (; k + 4 <= n0; k += 4) {
        const uint32_t w0 = *(const uint32_t*)&slist[k];
        const uint32_t w1 = *(const uint32_t*)&slist[k + 2];
        const uint2 v0 = *(const uint2*)&xb[(w0 & 0xffffu) * K_TOTAL + ch];
        const uint2 v1 = *(const uint2*)&xb[(w0 >> 16)     * K_TOTAL + ch];
        const uint2 v2 = *(const uint2*)&xb[(w1 & 0xffffu) * K_TOTAL + ch];
        const uint2 v3 = *(const uint2*)&xb[(w1 >> 16)     * K_TOTAL + ch];
        acc4(p0, v0); acc4(p1, v1); acc4(p0, v2); acc4(p1, v3);
    }
    for (; k < n0; k++) {
        acc4(p0, *(const uint2*)&xb[slist[k] * K_TOTAL + ch]);
    }
    float4 a0 = make_float4(p0.x + p1.x, p0.y + p1.y, p0.z + p1.z, p0.w + p1.w);

    float4 q0 = make_float4(0.f, 0.f, 0.f, 0.f);
    float4 q1 = make_float4(0.f, 0.f, 0.f, 0.f);
    k = 0;
    for (; k + 4 <= n1; k += 4) {
        const int i0 = slist[NN - 1 - k];
        const int i1 = slist[NN - 2 - k];
        const int i2 = slist[NN - 3 - k];
        const int i3 = slist[NN - 4 - k];
        const uint2 v0 = *(const uint2*)&xb[i0 * K_TOTAL + ch];
        const uint2 v1 = *(const uint2*)&xb[i1 * K_TOTAL + ch];
        const uint2 v2 = *(const uint2*)&xb[i2 * K_TOTAL + ch];
        const uint2 v3 = *(const uint2*)&xb[i3 * K_TOTAL + ch];
        acc4(q0, v0); acc4(q1, v1); acc4(q0, v2); acc4(q1, v3);
    }
    for (; k < n1; k++) {
        acc4(q0, *(const uint2*)&xb[slist[NN - 1 - k] * K_TOTAL + ch]);
    }
    float4 a1 = make_float4(q0.x + q1.x, q0.y + q1.y, q0.z + q1.z, q0.w + q1.w);

    __half* __restrict__ base =
        g_acat + (size_t)layer * ACAT_L + o * K_TOTAL;
    {
        __half2 h0 = __floats2half2_rn(a0.x * inv0, a0.y * inv0);
        __half2 h1 = __floats2half2_rn(a0.z * inv0, a0.w * inv0);
        uint2 u; u.x = *(uint32_t*)&h0; u.y = *(uint32_t*)&h1;
        *(uint2*)&base[DD + ch] = u;
    }
    {
        __half2 h0 = __floats2half2_rn(a1.x * inv1, a1.y * inv1);
        __half2 h1 = __floats2half2_rn(a1.z * inv1, a1.w * inv1);
        uint2 u; u.x = *(uint32_t*)&h0; u.y = *(uint32_t*)&h1;
        *(uint2*)&base[2 * DD + ch] = u;
    }
}

// ---------------------------------------------------------------------------
// Kernel 3: FP16 tensor-core GEMM (fp32 accum) + bias + ELU, cp.async
// 3-stage pipeline.  out[m,e] = elu( Acat[m,:] @ W[:,e] + bias[e] )
// M=8192, K=768, N=256. Block tile 64x128, 4 warps (2M x 2N), warp 32x64,
// mma.m16n8k16. Smem rows: 16 data words + 4 pad (stride 20) -> fragment
// banks (m*20 + w) mod 32 all distinct (conflict-free).
// layer 0: writes fp16 seg0 of acat[1]; layer 1: writes dout (fp32).
// ---------------------------------------------------------------------------
__device__ __forceinline__ void mma_f16(float c[4], const uint32_t a[4],
                                        uint32_t b0, uint32_t b1) {
    asm volatile(
        "mma.sync.aligned.m16n8k16.row.col.f32.f16.f16.f32 "
        "{%0,%1,%2,%3}, {%4,%5,%6,%7}, {%8,%9}, {%0,%1,%2,%3};"
        : "+f"(c[0]), "+f"(c[1]), "+f"(c[2]), "+f"(c[3])
        : "r"(a[0]), "r"(a[1]), "r"(a[2]), "r"(a[3]), "r"(b0), "r"(b1));
}

#define RW 20   // smem row stride in 32-bit words (16 data + 4 pad)

__global__ void __launch_bounds__(128)
rgcn_gemm_kernel(int layer, const float* __restrict__ bias,
                 float* __restrict__ dout) {
    __shared__ uint32_t As[STG][64][RW];     // [stage][m][kw]  (kw = k/2)
    __shared__ uint32_t Bs[STG][128][RW];    // [stage][n][kw]

    const __half* __restrict__ Ag = g_acat + (size_t)layer * ACAT_L;
    const __half* __restrict__ Bg = g_wT + (size_t)layer * W_L;

    const int t    = threadIdx.x;
    const int lane = t & 31;
    const int wid  = t >> 5;
    const int wm   = wid & 1;          // warp M (0..1)
    const int wn   = wid >> 1;         // warp N (0..1)
    const int gid  = lane >> 2;
    const int tig  = lane & 3;
    const int m0   = blockIdx.y * 64;
    const int e0   = blockIdx.x * 128;

    const uint32_t asb = (uint32_t)__cvta_generic_to_shared(As);
    const uint32_t bsb = (uint32_t)__cvta_generic_to_shared(Bs);

    // copy mappings (128 threads)
    const int arow = t >> 1;           // A row 0..63
    const int awo  = (t & 1) * 8;      // word offsets awo, awo+4

    auto issue_tile = [&](int tile) {
        if (tile < NT) {
            const int stage = tile % STG;
            const int kg = tile * BKT;
            #pragma unroll
            for (int c = 0; c < 2; c++) {
                const int wo = awo + c * 4;
                cp16(asb + (uint32_t)(((stage * 64 + arow) * RW + wo) * 4),
                     Ag + (size_t)(m0 + arow) * K_TOTAL + kg + wo * 2);
            }
            #pragma unroll
            for (int c = 0; c < 4; c++) {
                const int wo = c * 4;
                cp16(bsb + (uint32_t)(((stage * 128 + t) * RW + wo) * 4),
                     Bg + (size_t)(e0 + t) * K_TOTAL + kg + wo * 2);
            }
        }
        asm volatile("cp.async.commit_group;");
    };

    issue_tile(0);
    issue_tile(1);

    float acc[2][8][4] = {};

    for (int kt = 0; kt < NT; kt++) {
        asm volatile("cp.async.wait_group %0;" :: "n"(STG - 2));
        __syncthreads();

        issue_tile(kt + STG - 1);

        const int st = kt % STG;
        #pragma unroll
        for (int ks = 0; ks < 2; ks++) {
            const int kb = ks * 8;
            uint32_t af[2][4];
            #pragma unroll
            for (int mt = 0; mt < 2; mt++) {
                const int m = wm * 32 + mt * 16 + gid;
                af[mt][0] = As[st][m][kb + tig];
                af[mt][1] = As[st][m + 8][kb + tig];
                af[mt][2] = As[st][m][kb + tig + 4];
                af[mt][3] = As[st][m + 8][kb + tig + 4];
            }
            #pragma unroll
            for (int nt = 0; nt < 8; nt++) {
                const int n = wn * 64 + nt * 8 + gid;
                const uint32_t b0 = Bs[st][n][kb + tig];
                const uint32_t b1 = Bs[st][n][kb + tig + 4];
                mma_f16(acc[0][nt], af[0], b0, b1);
                mma_f16(acc[1][nt], af[1], b0, b1);
            }
        }
    }

    // epilogue: bias + ELU
    __half* __restrict__ outt = g_acat + ACAT_L;   // layer-1 seg0 (fp16)
    const float2* __restrict__ bias2 = (const float2*)bias;

    #pragma unroll
    for (int mt = 0; mt < 2; mt++) {
        const int mrow = m0 + wm * 32 + mt * 16 + gid;
        #pragma unroll
        for (int nt = 0; nt < 8; nt++) {
            const int col = e0 + wn * 64 + nt * 8 + 2 * tig;
            const float2 bb = bias2[col >> 1];
            float v0 = acc[mt][nt][0] + bb.x;
            float v1 = acc[mt][nt][1] + bb.y;
            float v2 = acc[mt][nt][2] + bb.x;
            float v3 = acc[mt][nt][3] + bb.y;
            v0 = (v0 > 0.f) ? v0 : expm1f(v0);
            v1 = (v1 > 0.f) ? v1 : expm1f(v1);
            v2 = (v2 > 0.f) ? v2 : expm1f(v2);
            v3 = (v3 > 0.f) ? v3 : expm1f(v3);
            if (layer == 0) {
                __half2 h0 = __floats2half2_rn(v0, v1);
                __half2 h1 = __floats2half2_rn(v2, v3);
                *(uint32_t*)&outt[(size_t)mrow * K_TOTAL + col]       = *(uint32_t*)&h0;
                *(uint32_t*)&outt[(size_t)(mrow + 8) * K_TOTAL + col] = *(uint32_t*)&h1;
            } else {
                *(float2*)&dout[(size_t)mrow * DD + col]       = make_float2(v0, v1);
                *(float2*)&dout[(size_t)(mrow + 8) * DD + col] = make_float2(v2, v3);
            }
        }
    }
}

// ---------------------------------------------------------------------------
// Launch: fused prologue, then per layer: agg -> FP16 GEMM+bias+ELU.
// ---------------------------------------------------------------------------
extern "C" void kernel_launch(void* const* d_in, const int* in_sizes, int n_in,
                              void* d_out, int out_size) {
    const float* x       = (const float*)d_in[0];
    const float* w_rel1  = (const float*)d_in[1];
    const float* w_root1 = (const float*)d_in[2];
    const float* b1      = (const float*)d_in[3];
    const float* w_rel2  = (const float*)d_in[4];
    const float* w_root2 = (const float*)d_in[5];
    const float* b2      = (const float*)d_in[6];
    const int* aug   = (const int*)d_in[7];
    const int* punct = (const int*)d_in[8];
    float* out = (float*)d_out;

    prologue_kernel<<<LIST_BLOCKS + CVT_BLOCKS, 256>>>(
        aug, punct, x, w_root1, w_rel1, w_root2, w_rel2);

    // Layer 1
    aggregate_kernel<<<dim3(NN, BS), 64>>>(0);
    rgcn_gemm_kernel<<<dim3(DD / 128, M_TOTAL / 64), 128>>>(0, b1, nullptr);

    // Layer 2
    aggregate_kernel<<<dim3(NN, BS), 64>>>(1);
    rgcn_gemm_kernel<<<dim3(DD / 128, M_TOTAL / 64), 128>>>(1, b2, out);
}

// round 17
// speedup vs baseline: 1.3069x; 1.0343x over previous
#include <cuda_runtime.h>
#include <cuda_fp16.h>
#include <cstdint>

#define BS 16
#define NN 512
#define DD 256
#define RR 2
#define M_TOTAL (BS * NN)           // 8192
#define K_TOTAL (3 * DD)            // 768
#define BKT 32                      // GEMM K-tile (2 x k16 steps)
#define NT (K_TOTAL / BKT)          // 24 tiles
#define STG 3                       // cp.async stages
#define ACAT_L ((size_t)M_TOTAL * K_TOTAL)
#define W_L    ((size_t)K_TOTAL * DD)

// Scratch (no allocations allowed).
__device__ __align__(16) unsigned short g_list[(size_t)BS * NN * NN];  // per (b,j): r0 front, r1 back
__device__ int    g_cnt[RR][BS * NN];
__device__ float  g_inv[RR][BS * NN];
__device__ __align__(16) __half g_acat[2 * ACAT_L];   // fp16 [layer][m][768] = [x|agg0|agg1]
__device__ __align__(16) __half g_wT[2 * W_L];        // fp16 [layer][n=256][k=768] (K-major)

__device__ __forceinline__ void cp16(uint32_t dst, const void* src) {
    asm volatile("cp.async.cg.shared.global [%0], [%1], 16;"
                 :: "r"(dst), "l"(src));
}

// ---------------------------------------------------------------------------
// Kernel 1: fused prologue. Blocks [0,256): mask transpose + compact
// neighbor-list build. Blocks [256,768): fp16 conversion of x (acat[0] seg0)
// + weights (transposed to [n][k] K-major for the fp16 MMA B operand).
// Adjacency is int32 on device (JAX downcasts int64).
// bit0 = punct (punct==1 && aug!=1), bit1 = aug (aug==1).
// ---------------------------------------------------------------------------
#define SMROW 516
#define LIST_BLOCKS 256
#define CVT_BLOCKS 512
#define XF4 (M_TOTAL * DD / 4)
#define WF4L (K_TOTAL * DD / 4)

__global__ void __launch_bounds__(256)
prologue_kernel(const int* __restrict__ aug,
                const int* __restrict__ punct,
                const float* __restrict__ x,
                const float* __restrict__ wroot1,
                const float* __restrict__ wrel1,
                const float* __restrict__ wroot2,
                const float* __restrict__ wrel2) {
    __shared__ unsigned char sm[32 * SMROW];
    const int t = threadIdx.x;

    if (blockIdx.x >= LIST_BLOCKS) {
        // ----- cvt job -----
        const int total = XF4 + 2 * WF4L;
        const int bid = blockIdx.x - LIST_BLOCKS;
        for (int idx = bid * 256 + t; idx < total; idx += CVT_BLOCKS * 256) {
            if (idx < XF4) {
                const int m = idx >> 6;
                const int dq = idx & 63;
                const float4 v = ((const float4*)x)[idx];
                __half2 h0 = __floats2half2_rn(v.x, v.y);
                __half2 h1 = __floats2half2_rn(v.z, v.w);
                uint2 u;
                u.x = *(uint32_t*)&h0;
                u.y = *(uint32_t*)&h1;
                *(uint2*)&g_acat[(size_t)m * K_TOTAL + dq * 4] = u;
            } else {
                const int j = idx - XF4;
                const int L = j / WF4L;
                const int j2 = j - L * WF4L;
                const int kk = j2 >> 6;            // 0..767
                const int nn = (j2 & 63) << 2;     // n base
                const float* src = (kk < DD)
                    ? (L ? wroot2 : wroot1) + kk * DD + nn
                    : (L ? wrel2 : wrel1) + (size_t)(kk - DD) * DD + nn;
                const float4 v = *(const float4*)src;
                __half* dst = g_wT + (size_t)L * W_L;
                dst[(size_t)(nn + 0) * K_TOTAL + kk] = __float2half_rn(v.x);
                dst[(size_t)(nn + 1) * K_TOTAL + kk] = __float2half_rn(v.y);
                dst[(size_t)(nn + 2) * K_TOTAL + kk] = __float2half_rn(v.z);
                dst[(size_t)(nn + 3) * K_TOTAL + kk] = __float2half_rn(v.w);
            }
        }
        return;
    }

    // ----- list job -----
    const int jt = blockIdx.x & 15;
    const int b  = blockIdx.x >> 4;
    const int w  = t >> 5;
    const int lane = t & 31;
    const int j0 = jt * 32;
    const size_t base = (size_t)b * NN * NN;

    const int i0w = w * 64;
    #pragma unroll 4
    for (int s = 0; s < 64; s++) {
        const int i = i0w + s;
        const size_t idx = base + (size_t)i * NN + j0 + lane;
        const int a = aug[idx];
        const int p = punct[idx];
        sm[lane * SMROW + i] = (a == 1) ? (unsigned char)2
                                        : ((p == 1) ? (unsigned char)1
                                                    : (unsigned char)0);
    }
    __syncthreads();

    const unsigned lt = (1u << lane) - 1u;
    #pragma unroll
    for (int q = 0; q < 4; q++) {
        const int jl = w * 4 + q;
        const unsigned char* __restrict__ row = sm + jl * SMROW;
        const size_t o = (size_t)b * NN + j0 + jl;
        unsigned short* __restrict__ lst = g_list + o * NN;

        int c0 = 0, c1 = 0;
        #pragma unroll 4
        for (int s = 0; s < NN; s += 32) {
            const unsigned char m = row[s + lane];
            const unsigned b0 = __ballot_sync(0xffffffffu, m & 1);
            const unsigned b1 = __ballot_sync(0xffffffffu, m & 2);
            if (m & 1) lst[c0 + __popc(b0 & lt)] = (unsigned short)(s + lane);
            if (m & 2) lst[NN - 1 - (c1 + __popc(b1 & lt))] = (unsigned short)(s + lane);
            c0 += __popc(b0);
            c1 += __popc(b1);
        }
        if (lane == 0) {
            g_cnt[0][o] = c0;
            g_cnt[1][o] = c1;
            g_inv[0][o] = 1.0f / (float)max(c0, 1);
            g_inv[1][o] = 1.0f / (float)max(c1, 1);
        }
    }
}

// ---------------------------------------------------------------------------
// Kernel 2: sparse mean-aggregation via compact lists, fp16 I/O.
// Block = (j, b), 64 threads; thread owns channels [4t,4t+3].
// Edge pairs are pre-combined with HADD2 (one fp16 add on ~N(0,2) pair-sums,
// ~3.5e-4 relative on agg terms) before fp32 accumulation — cuts fma-pipe
// ops per 4-edge group from 32 to 20.
// ---------------------------------------------------------------------------
__device__ __forceinline__ void acc4(float4& a, uint2 w) {
    const __half2 h0 = *(__half2*)&w.x;
    const __half2 h1 = *(__half2*)&w.y;
    const float2 f0 = __half22float2(h0);
    const float2 f1 = __half22float2(h1);
    a.x += f0.x; a.y += f0.y; a.z += f1.x; a.w += f1.y;
}

__device__ __forceinline__ void acc4_pair(float4& a, uint2 u, uint2 v) {
    const __half2 s0 = __hadd2(*(__half2*)&u.x, *(__half2*)&v.x);
    const __half2 s1 = __hadd2(*(__half2*)&u.y, *(__half2*)&v.y);
    const float2 f0 = __half22float2(s0);
    const float2 f1 = __half22float2(s1);
    a.x += f0.x; a.y += f0.y; a.z += f1.x; a.w += f1.y;
}

__global__ void __launch_bounds__(64)
aggregate_kernel(int layer) {
    const int j = blockIdx.x;
    const int b = blockIdx.y;
    const int t = threadIdx.x;
    const size_t o = (size_t)b * NN + j;

    __shared__ alignas(8) unsigned short slist[NN];
    __shared__ int sn0, sn1;
    __shared__ float si0, si1;
    if (t == 0) {
        sn0 = g_cnt[0][o]; sn1 = g_cnt[1][o];
        si0 = g_inv[0][o]; si1 = g_inv[1][o];
    }
    const unsigned short* __restrict__ lst = g_list + o * NN;
    #pragma unroll
    for (int k = 0; k < NN / 2 / 64; k++)
        ((unsigned int*)slist)[t + k * 64] = ((const unsigned int*)lst)[t + k * 64];
    __syncthreads();

    const int n0 = sn0, n1 = sn1;
    const float inv0 = si0, inv1 = si1;
    const __half* __restrict__ xb =
        g_acat + (size_t)layer * ACAT_L + (size_t)b * NN * K_TOTAL;
    const int ch = t * 4;   // channel base

    float4 p0 = make_float4(0.f, 0.f, 0.f, 0.f);
    float4 p1 = make_float4(0.f, 0.f, 0.f, 0.f);
    int k = 0;
    for (; k + 4 <= n0; k += 4) {
        const uint32_t w0 = *(const uint32_t*)&slist[k];
        const uint32_t w1 = *(const uint32_t*)&slist[k + 2];
        const uint2 v0 = *(const uint2*)&xb[(w0 & 0xffffu) * K_TOTAL + ch];
        const uint2 v1 = *(const uint2*)&xb[(w0 >> 16)     * K_TOTAL + ch];
        const uint2 v2 = *(const uint2*)&xb[(w1 & 0xffffu) * K_TOTAL + ch];
        const uint2 v3 = *(const uint2*)&xb[(w1 >> 16)     * K_TOTAL + ch];
        acc4_pair(p0, v0, v2);
        acc4_pair(p1, v1, v3);
    }
    for (; k < n0; k++) {
        acc4(p0, *(const uint2*)&xb[slist[k] * K_TOTAL + ch]);
    }
    float4 a0 = make_float4(p0.x + p1.x, p0.y + p1.y, p0.z + p1.z, p0.w + p1.w);

    float4 q0 = make_float4(0.f, 0.f, 0.f, 0.f);
    float4 q1 = make_float4(0.f, 0.f, 0.f, 0.f);
    k = 0;
    for (; k + 4 <= n1; k += 4) {
        const int i0 = slist[NN - 1 - k];
        const int i1 = slist[NN - 2 - k];
        const int i2 = slist[NN - 3 - k];
        const int i3 = slist[NN - 4 - k];
        const uint2 v0 = *(const uint2*)&xb[i0 * K_TOTAL + ch];
        const uint2 v1 = *(const uint2*)&xb[i1 * K_TOTAL + ch];
        const uint2 v2 = *(const uint2*)&xb[i2 * K_TOTAL + ch];
        const uint2 v3 = *(const uint2*)&xb[i3 * K_TOTAL + ch];
        acc4_pair(q0, v0, v2);
        acc4_pair(q1, v1, v3);
    }
    for (; k < n1; k++) {
        acc4(q0, *(const uint2*)&xb[slist[NN - 1 - k] * K_TOTAL + ch]);
    }
    float4 a1 = make_float4(q0.x + q1.x, q0.y + q1.y, q0.z + q1.z, q0.w + q1.w);

    __half* __restrict__ base =
        g_acat + (size_t)layer * ACAT_L + o * K_TOTAL;
    {
        __half2 h0 = __floats2half2_rn(a0.x * inv0, a0.y * inv0);
        __half2 h1 = __floats2half2_rn(a0.z * inv0, a0.w * inv0);
        uint2 u; u.x = *(uint32_t*)&h0; u.y = *(uint32_t*)&h1;
        *(uint2*)&base[DD + ch] = u;
    }
    {
        __half2 h0 = __floats2half2_rn(a1.x * inv1, a1.y * inv1);
        __half2 h1 = __floats2half2_rn(a1.z * inv1, a1.w * inv1);
        uint2 u; u.x = *(uint32_t*)&h0; u.y = *(uint32_t*)&h1;
        *(uint2*)&base[2 * DD + ch] = u;
    }
}

// ---------------------------------------------------------------------------
// Kernel 3: FP16 tensor-core GEMM (fp32 accum) + bias + ELU, cp.async
// 3-stage pipeline.  out[m,e] = elu( Acat[m,:] @ W[:,e] + bias[e] )
// M=8192, K=768, N=256. Block tile 64x128, 4 warps (2M x 2N), warp 32x64,
// mma.m16n8k16. Smem row stride 20 words -> conflict-free fragments.
// layer 0: writes fp16 seg0 of acat[1]; layer 1: writes dout (fp32).
// ---------------------------------------------------------------------------
__device__ __forceinline__ void mma_f16(float c[4], const uint32_t a[4],
                                        uint32_t b0, uint32_t b1) {
    asm volatile(
        "mma.sync.aligned.m16n8k16.row.col.f32.f16.f16.f32 "
        "{%0,%1,%2,%3}, {%4,%5,%6,%7}, {%8,%9}, {%0,%1,%2,%3};"
        : "+f"(c[0]), "+f"(c[1]), "+f"(c[2]), "+f"(c[3])
        : "r"(a[0]), "r"(a[1]), "r"(a[2]), "r"(a[3]), "r"(b0), "r"(b1));
}

#define RW 20   // smem row stride in 32-bit words (16 data + 4 pad)

__global__ void __launch_bounds__(128)
rgcn_gemm_kernel(int layer, const float* __restrict__ bias,
                 float* __restrict__ dout) {
    __shared__ uint32_t As[STG][64][RW];     // [stage][m][kw]  (kw = k/2)
    __shared__ uint32_t Bs[STG][128][RW];    // [stage][n][kw]

    const __half* __restrict__ Ag = g_acat + (size_t)layer * ACAT_L;
    const __half* __restrict__ Bg = g_wT + (size_t)layer * W_L;

    const int t    = threadIdx.x;
    const int lane = t & 31;
    const int wid  = t >> 5;
    const int wm   = wid & 1;          // warp M (0..1)
    const int wn   = wid >> 1;         // warp N (0..1)
    const int gid  = lane >> 2;
    const int tig  = lane & 3;
    const int m0   = blockIdx.y * 64;
    const int e0   = blockIdx.x * 128;

    const uint32_t asb = (uint32_t)__cvta_generic_to_shared(As);
    const uint32_t bsb = (uint32_t)__cvta_generic_to_shared(Bs);

    // copy mappings (128 threads)
    const int arow = t >> 1;           // A row 0..63
    const int awo  = (t & 1) * 8;      // word offsets awo, awo+4

    auto issue_tile = [&](int tile) {
        if (tile < NT) {
            const int stage = tile % STG;
            const int kg = tile * BKT;
            #pragma unroll
            for (int c = 0; c < 2; c++) {
                const int wo = awo + c * 4;
                cp16(asb + (uint32_t)(((stage * 64 + arow) * RW + wo) * 4),
                     Ag + (size_t)(m0 + arow) * K_TOTAL + kg + wo * 2);
            }
            #pragma unroll
            for (int c = 0; c < 4; c++) {
                const int wo = c * 4;
                cp16(bsb + (uint32_t)(((stage * 128 + t) * RW + wo) * 4),
                     Bg + (size_t)(e0 + t) * K_TOTAL + kg + wo * 2);
            }
        }
        asm volatile("cp.async.commit_group;");
    };

    issue_tile(0);
    issue_tile(1);

    float acc[2][8][4] = {};

    for (int kt = 0; kt < NT; kt++) {
        asm volatile("cp.async.wait_group %0;" :: "n"(STG - 2));
        __syncthreads();

        issue_tile(kt + STG - 1);

        const int st = kt % STG;
        #pragma unroll
        for (int ks = 0; ks < 2; ks++) {
            const int kb = ks * 8;
            uint32_t af[2][4];
            #pragma unroll
            for (int mt = 0; mt < 2; mt++) {
                const int m = wm * 32 + mt * 16 + gid;
                af[mt][0] = As[st][m][kb + tig];
                af[mt][1] = As[st][m + 8][kb + tig];
                af[mt][2] = As[st][m][kb + tig + 4];
                af[mt][3] = As[st][m + 8][kb + tig + 4];
            }
            #pragma unroll
            for (int nt = 0; nt < 8; nt++) {
                const int n = wn * 64 + nt * 8 + gid;
                const uint32_t b0 = Bs[st][n][kb + tig];
                const uint32_t b1 = Bs[st][n][kb + tig + 4];
                mma_f16(acc[0][nt], af[0], b0, b1);
                mma_f16(acc[1][nt], af[1], b0, b1);
            }
        }
    }

    // epilogue: bias + ELU
    __half* __restrict__ outt = g_acat + ACAT_L;   // layer-1 seg0 (fp16)
    const float2* __restrict__ bias2 = (const float2*)bias;

    #pragma unroll
    for (int mt = 0; mt < 2; mt++) {
        const int mrow = m0 + wm * 32 + mt * 16 + gid;
        #pragma unroll
        for (int nt = 0; nt < 8; nt++) {
            const int col = e0 + wn * 64 + nt * 8 + 2 * tig;
            const float2 bb = bias2[col >> 1];
            float v0 = acc[mt][nt][0] + bb.x;
            float v1 = acc[mt][nt][1] + bb.y;
            float v2 = acc[mt][nt][2] + bb.x;
            float v3 = acc[mt][nt][3] + bb.y;
            v0 = (v0 > 0.f) ? v0 : expm1f(v0);
            v1 = (v1 > 0.f) ? v1 : expm1f(v1);
            v2 = (v2 > 0.f) ? v2 : expm1f(v2);
            v3 = (v3 > 0.f) ? v3 : expm1f(v3);
            if (layer == 0) {
                __half2 h0 = __floats2half2_rn(v0, v1);
                __half2 h1 = __floats2half2_rn(v2, v3);
                *(uint32_t*)&outt[(size_t)mrow * K_TOTAL + col]       = *(uint32_t*)&h0;
                *(uint32_t*)&outt[(size_t)(mrow + 8) * K_TOTAL + col] = *(uint32_t*)&h1;
            } else {
                *(float2*)&dout[(size_t)mrow * DD + col]       = make_float2(v0, v1);
                *(float2*)&dout[(size_t)(mrow + 8) * DD + col] = make_float2(v2, v3);
            }
        }
    }
}

// ---------------------------------------------------------------------------
// Launch: fused prologue, then per layer: agg -> FP16 GEMM+bias+ELU.
// ---------------------------------------------------------------------------
extern "C" void kernel_launch(void* const* d_in, const int* in_sizes, int n_in,
                              void* d_out, int out_size) {
    const float* x       = (const float*)d_in[0];
    const float* w_rel1  = (const float*)d_in[1];
    const float* w_root1 = (const float*)d_in[2];
    const float* b1      = (const float*)d_in[3];
    const float* w_rel2  = (const float*)d_in[4];
    const float* w_root2 = (const float*)d_in[5];
    const float* b2      = (const float*)d_in[6];
    const int* aug   = (const int*)d_in[7];
    const int* punct = (const int*)d_in[8];
    float* out = (float*)d_out;

    prologue_kernel<<<LIST_BLOCKS + CVT_BLOCKS, 256>>>(
        aug, punct, x, w_root1, w_rel1, w_root2, w_rel2);

    // Layer 1
    aggregate_kernel<<<dim3(NN, BS), 64>>>(0);
    rgcn_gemm_kernel<<<dim3(DD / 128, M_TOTAL / 64), 128>>>(0, b1, nullptr);

    // Layer 2
    aggregate_kernel<<<dim3(NN, BS), 64>>>(1);
    rgcn_gemm_kernel<<<dim3(DD / 128, M_TOTAL / 64), 128>>>(1, b2, out);
}